// round 14
// baseline (speedup 1.0000x reference)
#include <cuda_runtime.h>
#include <math.h>

#define NWIRES 9
#define NLAYERS 4
#define DDIM 512
#define BATCH 64
#define PPAR 72
#define NGATES 36
#define EMBED 512

typedef unsigned long long u64;

// Scratch (allocation-free)
__device__ float g_params[BATCH * PPAR];

// dynamic smem layout for the sim kernel
#define SM_GF   0                        // 144 floats
#define SM_PLO  576                      // float2[4][32]
#define SM_PHI  1600                     // float2[4][16]
#define SM_PP   2112                     // 80 floats (params accum)
#define SM_PH   2560                     // float2[4][512] = 16384 B
#define SM_BUF  18944                    // 16 warps x 512 float2 = 65536 B
#define SM_TOTAL (18944 + 65536)

// ---- f32x2 helpers (sm_103a packed fp32) ----
__device__ __forceinline__ u64 pk2(float x, float y) {
    u64 d; asm("mov.b64 %0,{%1,%2};" : "=l"(d) : "f"(x), "f"(y)); return d;
}
__device__ __forceinline__ float2 upk2(u64 v) {
    float2 r; asm("mov.b64 {%0,%1},%2;" : "=f"(r.x), "=f"(r.y) : "l"(v)); return r;
}
__device__ __forceinline__ u64 fma2(u64 a, u64 b, u64 c) {
    u64 d; asm("fma.rn.f32x2 %0,%1,%2,%3;" : "=l"(d) : "l"(a), "l"(b), "l"(c)); return d;
}

// CNOT-ring permutation (verified R1): new[n] = old[pi(n)]
__device__ __forceinline__ int cperm(int p) {
    int n = (p ^ (p >> 1)) & 0x7F;
    n |= (((p >> 7) ^ (p >> 8) ^ p) & 1) << 7;
    n |= (((p >> 8) ^ p) & 1) << 8;
    return n;
}
// inverse of cperm (GF(2)-linear; validated R4-R13)
__device__ __forceinline__ int pinv9(int n) {
    int pb = __popc(n) & 1;
    int acc = pb, run = pb;
#pragma unroll
    for (int j = 0; j < 7; j++) { run ^= (n >> j) & 1; acc |= run << (j + 1); }
    acc |= (((n >> 8) & 1) ^ pb) << 8;
    return acc;
}
// B->A swizzle (GF(2)-rank-verified conflict-free)
__device__ __forceinline__ int f2s(int a) {
    return a ^ ((a >> 5) & 15) ^ ((a >> 4) & 16);
}

// ---------------------------------------------------------------------------
// Sim kernel: fused MLP + circuit simulation. One column per warp.
// State: 16 packed u64 amps {re,im}. Fast-Givens gates apply the same real
// coefficient to re and im -> 1 fma2 per value per wire. State stays packed
// through gates AND the float2 smem transposes; unpacked only at phases and
// the wire-4 shfl halves.
// Layout A: lane=p[8:4], slot=p[3:0]; layout B: lane=p[4:0], slot=p[8:5].
// ---------------------------------------------------------------------------
__global__ __launch_bounds__(512, 2) void k2_sim(
        float* __restrict__ out,
        const float* __restrict__ t,  const float* __restrict__ w1,
        const float* __restrict__ b1, const float* __restrict__ w2,
        const float* __restrict__ b2) {
    const int b    = blockIdx.x >> 5;   // batch
    const int grp  = blockIdx.x & 31;   // 32 groups x 16 columns
    const int wid  = threadIdx.x >> 5;
    const int lane = threadIdx.x & 31;
    const int col  = grp * 16 + wid;
    const int tid  = threadIdx.x;

    extern __shared__ char dsm[];
    float*  gf   = (float*)(dsm + SM_GF);          // 36 gates x {c,s,cp,sp}
    float2* plo  = (float2*)(dsm + SM_PLO);        // [4][32]
    float2* phi  = (float2*)(dsm + SM_PHI);        // [4][16]
    float*  pp   = (float*)(dsm + SM_PP);          // params accum
    float2* ph   = (float2*)(dsm + SM_PH);         // [4][512]
    u64*    bufu = (u64*)(dsm + SM_BUF);           // 16 warps x 512 u64
    float (*tile)[513] = (float (*)[513])bufu;     // epilogue alias
    float*  hbuf = (float*)bufu;                   // MLP hidden alias (prologue)

    // ==== fused MLP: params = silu(t*w1+b1) @ w2 + b2 ====
    {
        float tv = t[b];
        float x = fmaf(tv, w1[tid], b1[tid]);
        if (tid < PPAR) pp[tid] = 0.f;
        hbuf[tid] = x / (1.f + expf(-x));
    }
    __syncthreads();
    {
        float acc0 = 0.f, acc1 = 0.f, acc2 = 0.f;
        const float* w2base = w2 + (wid * 32) * PPAR;
#pragma unroll 8
        for (int k = 0; k < 32; k++) {
            float hv = hbuf[wid * 32 + k];
            const float* wrow = w2base + k * PPAR;
            acc0 = fmaf(hv, wrow[lane], acc0);
            acc1 = fmaf(hv, wrow[lane + 32], acc1);
            if (lane < 8) acc2 = fmaf(hv, wrow[lane + 64], acc2);
        }
        atomicAdd(&pp[lane], acc0);
        atomicAdd(&pp[lane + 32], acc1);
        if (lane < 8) atomicAdd(&pp[lane + 64], acc2);
    }
    __syncthreads();
    if (tid < PPAR) {
        float v = pp[tid] + b2[tid];
        pp[tid] = v;
        if (grp == 0) g_params[b * PPAR + tid] = v;
    }
    __syncthreads();
    // ==== gate trig ====
    if (tid < NGATES) {
        float* dst = &gf[tid * 4];
        dst[0] = cosf(0.5f * pp[2 * tid]);
        dst[1] = sinf(0.5f * pp[2 * tid]);
        dst[2] = cosf(0.5f * pp[2 * tid + 1]);
        dst[3] = sinf(0.5f * pp[2 * tid + 1]);
    }
    __syncthreads();
    // ==== phase subtables ====
    if (tid < 128) {           // plo[L][l]: wires 4..8 (n bits 4..0)
        const int L = tid >> 5, l = tid & 31;
        float pr = 1.f, pi_ = 0.f;
#pragma unroll
        for (int w = 4; w < 9; w++) {
            float cp = gf[(L * 9 + w) * 4 + 2];
            float sp = gf[(L * 9 + w) * 4 + 3];
            float sg = ((l >> (8 - w)) & 1) ? sp : -sp;
            float nr = fmaf(pr, cp, -pi_ * sg);
            float ni = fmaf(pr, sg,  pi_ * cp);
            pr = nr; pi_ = ni;
        }
        plo[L * 32 + l] = make_float2(pr, pi_);
    } else if (tid < 192) {    // phi[L][hh]: wires 0..3 (n bits 8..5), C_L folded (L>=1)
        const int L = (tid - 128) >> 4, hh = tid & 15;
        float pr = 1.f, pi_ = 0.f;
#pragma unroll
        for (int w = 0; w < 4; w++) {
            float cp = gf[(L * 9 + w) * 4 + 2];
            float sp = gf[(L * 9 + w) * 4 + 3];
            float sg = ((hh >> (3 - w)) & 1) ? sp : -sp;
            float nr = fmaf(pr, cp, -pi_ * sg);
            float ni = fmaf(pr, sg,  pi_ * cp);
            pr = nr; pi_ = ni;
        }
        if (L >= 1) {
            float C = 1.f;
#pragma unroll
            for (int w = 0; w < 9; w++) C *= gf[(L * 9 + w) * 4];
            pr *= C; pi_ *= C;
        }
        phi[L * 16 + hh] = make_float2(pr, pi_);
    }
    __syncthreads();
    // ==== full tables: ph[L][.] = plo*phi ====
    // L0: layout-A index of p = pinv9(n): ((p&15)<<5)|(p>>4).  L1-3: linear n.
    {
        const int n = tid;
#pragma unroll
        for (int L = 0; L < NLAYERS; L++) {
            float2 lo = plo[L * 32 + (n & 31)];
            float2 hi = phi[L * 16 + (n >> 5)];
            float pr  = fmaf(lo.x, hi.x, -lo.y * hi.y);
            float pi_ = fmaf(lo.x, hi.y,  lo.y * hi.x);
            int idx = n;
            if (L == 0) {
                int p = pinv9(n);
                idx = ((p & 15) << 5) | (p >> 4);
            }
            ph[L * 512 + idx] = make_float2(pr, pi_);
        }
    }
    __syncthreads();

    const int l0 = lane & 1, l1 = (lane >> 1) & 1, l2 = (lane >> 2) & 1;
    const int l3 = (lane >> 3) & 1, l4 = (lane >> 4) & 1;

    u64 amp[16];   // packed {re, im} per slot

    // ---- layer 0: analytic (validated R4-R13), packed init ----
    {
        float E0a, E0b, E1a, E1b, E2a, E2b, E3a, E3b, E4a, E4b;
        float E5a, E5b, E6a, E6b, E7a, E7b, E8a, E8b;
#define MKE(W, A, Bv) { float c_ = gf[(W)*4], s_ = gf[(W)*4+1]; \
        int cb = (col >> (8-(W))) & 1; A = cb ? -s_ : c_; Bv = cb ? c_ : s_; }
        MKE(0, E0a, E0b) MKE(1, E1a, E1b) MKE(2, E2a, E2b)
        MKE(3, E3a, E3b) MKE(4, E4a, E4b) MKE(5, E5a, E5b)
        MKE(6, E6a, E6b) MKE(7, E7a, E7b) MKE(8, E8a, E8b)
#undef MKE
        float Plane = ((l0 ^ l1) ? E4b : E4a)
                    * ((l1 ^ l2) ? E3b : E3a)
                    * ((l2 ^ l3) ? E2b : E2a);
        float q3_0 = l0 ? E5b : E5a;
        float q3_1 = l0 ? E5a : E5b;
        int x34 = l3 ^ l4;
        float q78_0 = (x34 ? E1b : E1a) * (l4 ? E0b : E0a);
        float q78_1 = (x34 ? E1a : E1b) * (l4 ? E0a : E0b);
#pragma unroll
        for (int r = 0; r < 16; r++) {
            const int r0 = r & 1, r1 = (r >> 1) & 1, r2 = (r >> 2) & 1, r3 = (r >> 3) & 1;
            float av = Plane
                     * (r3 ? q3_1 : q3_0)
                     * (r0 ? q78_1 : q78_0)
                     * ((r0 ^ r1) ? E8b : E8a)
                     * ((r1 ^ r2) ? E7b : E7a)
                     * ((r2 ^ r3) ? E6b : E6a);
            float2 p0 = ph[(r << 5) | lane];
            amp[r] = pk2(av * p0.x, av * p0.y);
        }
    }

    // exchange addressing (validated R8/R13)
    u64* wb = bufu + wid * 512;
    const int awb = (lane << 4) ^ lane;         // A-write: addr = awb ^ r
    const int lb  = lane ^ (lane >> 4);         // B-read:  addr = s*34 ^ lb
    const int paBase = f2s(cperm(lane << 4));   // exact

#pragma unroll 1
    for (int L = 1; L < NLAYERS; L++) {
        const float* gL = gf + L * 36;
        // ---- layout A: wires 5..8, packed fast-Givens ----
#pragma unroll
        for (int w = 5; w < 9; w++) {
            float tg = __fdividef(gL[w * 4 + 1], gL[w * 4]);
            u64 tg2  = pk2(tg, tg);
            u64 ntg2 = pk2(-tg, -tg);
            const int bit = 1 << (8 - w);
#pragma unroll
            for (int ra = 0; ra < 16; ra++) {
                if (ra & bit) continue;
                const int rb = ra | bit;
                u64 x = amp[ra], y = amp[rb];
                amp[ra] = fma2(ntg2, y, x);
                amp[rb] = fma2(tg2, x, y);
            }
        }
        // ---- transpose A->B (u64, swizzle x^(x>>4)) ----
#pragma unroll
        for (int r = 0; r < 16; r++) wb[awb ^ r] = amp[r];
        __syncwarp();
#pragma unroll
        for (int s = 0; s < 16; s++) amp[s] = wb[(s * 34) ^ lb];
        __syncwarp();
        // ---- layout B: wires 0..3, packed fast-Givens ----
#pragma unroll
        for (int w = 0; w < 4; w++) {
            float tg = __fdividef(gL[w * 4 + 1], gL[w * 4]);
            u64 tg2  = pk2(tg, tg);
            u64 ntg2 = pk2(-tg, -tg);
            const int bit = 1 << (3 - w);
#pragma unroll
            for (int sa = 0; sa < 16; sa++) {
                if (sa & bit) continue;
                const int sb = sa | bit;
                u64 x = amp[sa], y = amp[sb];
                amp[sa] = fma2(ntg2, y, x);
                amp[sb] = fma2(tg2, x, y);
            }
        }
        // ---- wire 4: lane bit 4 (shfl halves, packed fma) ----
        {
            float tg = __fdividef(gL[4 * 4 + 1], gL[4 * 4]);
            float bt = l4 ? tg : -tg;
            u64 bt2 = pk2(bt, bt);
#pragma unroll
            for (int s = 0; s < 16; s++) {
                float2 av = upk2(amp[s]);
                float ore = __shfl_xor_sync(0xffffffffu, av.x, 16);
                float oim = __shfl_xor_sync(0xffffffffu, av.y, 16);
                amp[s] = fma2(bt2, pk2(ore, oim), amp[s]);
            }
        }
        if (L < 3) {
            // ---- phase (C_L folded), layout B: n = (s<<5)|lane ----
            const float2* phL = ph + L * 512;
#pragma unroll
            for (int s = 0; s < 16; s++) {
                float2 av = upk2(amp[s]);
                float2 pq = phL[(s << 5) | lane];
                amp[s] = pk2(fmaf(pq.x, av.x, -(pq.y * av.y)),
                             fmaf(pq.y, av.x,  (pq.x * av.y)));
            }
            // ---- transpose B->A with perm folded (u64, swizzle f2s) ----
#pragma unroll
            for (int s = 0; s < 16; s++) {
                int a = ((s << 5) ^ (s & 15) ^ ((s & 8) << 1)) ^ lane;
                wb[a] = amp[s];
            }
            __syncwarp();
#pragma unroll
            for (int r = 0; r < 16; r++) amp[r] = wb[paBase ^ f2s(cperm(r))];
            __syncwarp();
        }
    }

    // ---- L3 final phase: re-only ----
    float re[16];
    {
        const float2* phL = ph + 3 * 512;
#pragma unroll
        for (int s = 0; s < 16; s++) {
            float2 av = upk2(amp[s]);
            float2 pq = phL[(s << 5) | lane];
            re[s] = fmaf(pq.x, av.x, -(pq.y * av.y));
        }
    }

    __syncthreads();   // all warps done with wb; alias buf as tile

    // direct tile store with CNOT perm folded: j = pinv9((s<<5)|lane)
    {
        const int pl = pinv9(lane);
#pragma unroll
        for (int s = 0; s < 16; s++)
            tile[wid][pinv9(s << 5) ^ pl] = re[s];
    }
    __syncthreads();

    // coalesced write: out[b][j][grp*16 + c]
    float* obase = out + (size_t)b * DDIM * DDIM + grp * 16;
    const int c  = tid & 15;
    const int j0 = tid >> 4;   // 0..31
#pragma unroll
    for (int k = 0; k < 16; k++) {
        int j = k * 32 + j0;
        obase[(size_t)j * DDIM + c] = tile[c][j];
    }
}

// ---------------------------------------------------------------------------
// K3: rank-2 expm update; TWO rows per warp for ILP (independent reduction
// chains interleaved; v and theta scalars shared).
// C[i,j] += (a1*u0 - a2*Uv_i) v_j (j>=1); C[i,0] = ct*u0 - a1*Uv_i.
// ---------------------------------------------------------------------------
__global__ void k3_update(float* __restrict__ out) {
    const int gw   = (blockIdx.x * blockDim.x + threadIdx.x) >> 5;  // 0..16383
    const int lane = threadIdx.x & 31;
    const int b  = gw >> 8;          // 256 warps per batch
    const int i0 = (gw & 255) << 1;  // rows i0, i0+1
    if (b >= BATCH) return;

    const float* gp = g_params + b * PPAR;
    float* rowA = out + ((size_t)b * DDIM + i0) * DDIM;
    float* rowB = rowA + DDIM;

    float v0 = (lane >= 1) ? 0.01f * gp[lane] : 0.f;
    float v1 = 0.01f * gp[lane + 32];
    float v2 = (lane < 8) ? 0.01f * gp[lane + 64] : 0.f;

    float ra0 = rowA[lane], ra1 = rowA[lane + 32];
    float ra2 = (lane < 8) ? rowA[lane + 64] : 0.f;
    float rb0 = rowB[lane], rb1 = rowB[lane + 32];
    float rb2 = (lane < 8) ? rowB[lane + 64] : 0.f;

    float u0A = __shfl_sync(0xffffffffu, ra0, 0);
    float u0B = __shfl_sync(0xffffffffu, rb0, 0);

    float uvA = fmaf(ra0, v0, fmaf(ra1, v1, ra2 * v2));
    float uvB = fmaf(rb0, v0, fmaf(rb1, v1, rb2 * v2));
    float s2  = fmaf(v0, v0, fmaf(v1, v1, v2 * v2));
#pragma unroll
    for (int d = 16; d >= 1; d >>= 1) {
        uvA += __shfl_xor_sync(0xffffffffu, uvA, d);
        uvB += __shfl_xor_sync(0xffffffffu, uvB, d);
        s2  += __shfl_xor_sync(0xffffffffu, s2, d);
    }

    float th = sqrtf(s2);
    float ct = cosf(th);
    float c1, c2;
    if (th > 1e-6f) { c1 = sinf(th) / th; c2 = (1.f - ct) / s2; }
    else            { c1 = 1.f - s2 * (1.f / 6.f); c2 = 0.5f; }
    float fA = fmaf(c1, u0A, -c2 * uvA);
    float fB = fmaf(c1, u0B, -c2 * uvB);

    rowA[lane]      = (lane == 0) ? fmaf(u0A, ct, -c1 * uvA) : fmaf(fA, v0, ra0);
    rowA[lane + 32] = fmaf(fA, v1, ra1);
    if (lane < 8) rowA[lane + 64] = fmaf(fA, v2, ra2);
    rowB[lane]      = (lane == 0) ? fmaf(u0B, ct, -c1 * uvB) : fmaf(fB, v0, rb0);
    rowB[lane + 32] = fmaf(fB, v1, rb1);
    if (lane < 8) rowB[lane + 64] = fmaf(fB, v2, rb2);
}

// ---------------------------------------------------------------------------
extern "C" void kernel_launch(void* const* d_in, const int* in_sizes, int n_in,
                              void* d_out, int out_size) {
    const float* t  = (const float*)d_in[0];
    const float* w1 = (const float*)d_in[1];
    const float* b1 = (const float*)d_in[2];
    const float* w2 = (const float*)d_in[3];
    const float* b2 = (const float*)d_in[4];
    float* out = (float*)d_out;

    cudaFuncSetAttribute(k2_sim, cudaFuncAttributeMaxDynamicSharedMemorySize,
                         SM_TOTAL);

    k2_sim<<<BATCH * 32, 512, SM_TOTAL>>>(out, t, w1, b1, w2, b2);
    k3_update<<<(BATCH * DDIM / 2) / 8, 256>>>(out);
}

// round 15
// speedup vs baseline: 1.4651x; 1.4651x over previous
#include <cuda_runtime.h>
#include <math.h>

#define NWIRES 9
#define NLAYERS 4
#define DDIM 512
#define BATCH 64
#define PPAR 72
#define NGATES 36
#define EMBED 512

// Scratch (allocation-free)
__device__ float g_params[BATCH * PPAR];

// dynamic smem layout for the sim kernel
#define SM_GF   0                        // 144 floats
#define SM_PLO  576                      // float2[4][32]
#define SM_PHI  1600                     // float2[4][16]
#define SM_PP   2112                     // 80 floats (params accum)
#define SM_PH   2560                     // float2[4][512] = 16384 B
#define SM_BUF  18944                    // 16 warps x 512 float2 = 65536 B
#define SM_TOTAL (18944 + 65536)

// CNOT-ring permutation (verified R1): new[n] = old[pi(n)]
__device__ __forceinline__ int cperm(int p) {
    int n = (p ^ (p >> 1)) & 0x7F;
    n |= (((p >> 7) ^ (p >> 8) ^ p) & 1) << 7;
    n |= (((p >> 8) ^ p) & 1) << 8;
    return n;
}
// inverse of cperm (GF(2)-linear; validated R4-R13)
__device__ __forceinline__ int pinv9(int n) {
    int pb = __popc(n) & 1;
    int acc = pb, run = pb;
#pragma unroll
    for (int j = 0; j < 7; j++) { run ^= (n >> j) & 1; acc |= run << (j + 1); }
    acc |= (((n >> 8) & 1) ^ pb) << 8;
    return acc;
}
// B->A swizzle (GF(2)-rank-verified conflict-free)
__device__ __forceinline__ int f2s(int a) {
    return a ^ ((a >> 5) & 15) ^ ((a >> 4) & 16);
}

// ---------------------------------------------------------------------------
// Sim kernel: fused MLP + circuit simulation. One column per warp.
// Layout A: lane=p[8:4], slot=p[3:0] (wires 5-8 register-local)
// Layout B: lane=p[4:0], slot=p[8:5] (wires 0-3 register-local)
// Wire 4 (lane bit 4 in layout B) is fused into the A->B transpose READ:
// gates on distinct wires commute, and the partner value (lane^16) lives at
// buffer address a^17 (lb' = lane^16 ^ ((lane>>4)^1) = lb^17). This replaces
// 32 SHFL/layer with 16 LDS.64/layer.
// Phase tables factorized: ph(n) = plo(n&31)*phi(n>>5); C_L folded into phi.
// L0 table stored at the LAYOUT-A index of p=pinv9(n).
// ---------------------------------------------------------------------------
__global__ __launch_bounds__(512, 2) void k2_sim(
        float* __restrict__ out,
        const float* __restrict__ t,  const float* __restrict__ w1,
        const float* __restrict__ b1, const float* __restrict__ w2,
        const float* __restrict__ b2) {
    const int b    = blockIdx.x >> 5;   // batch
    const int grp  = blockIdx.x & 31;   // 32 groups x 16 columns
    const int wid  = threadIdx.x >> 5;
    const int lane = threadIdx.x & 31;
    const int col  = grp * 16 + wid;
    const int tid  = threadIdx.x;

    extern __shared__ char dsm[];
    float*  gf   = (float*)(dsm + SM_GF);          // 36 gates x {c,s,cp,sp}
    float2* plo  = (float2*)(dsm + SM_PLO);        // [4][32]
    float2* phi  = (float2*)(dsm + SM_PHI);        // [4][16]
    float*  pp   = (float*)(dsm + SM_PP);          // params accum
    float2* ph   = (float2*)(dsm + SM_PH);         // [4][512]
    float2* buf2 = (float2*)(dsm + SM_BUF);        // 16 warps x 512 float2
    float (*tile)[513] = (float (*)[513])buf2;     // epilogue alias
    float*  hbuf = (float*)buf2;                   // MLP hidden alias (prologue)

    // ==== fused MLP: params = silu(t*w1+b1) @ w2 + b2 ====
    {
        float tv = t[b];
        float x = fmaf(tv, w1[tid], b1[tid]);
        if (tid < PPAR) pp[tid] = 0.f;
        hbuf[tid] = x / (1.f + expf(-x));
    }
    __syncthreads();
    {
        float acc0 = 0.f, acc1 = 0.f, acc2 = 0.f;
        const float* w2base = w2 + (wid * 32) * PPAR;
#pragma unroll 8
        for (int k = 0; k < 32; k++) {
            float hv = hbuf[wid * 32 + k];
            const float* wrow = w2base + k * PPAR;
            acc0 = fmaf(hv, wrow[lane], acc0);
            acc1 = fmaf(hv, wrow[lane + 32], acc1);
            if (lane < 8) acc2 = fmaf(hv, wrow[lane + 64], acc2);
        }
        atomicAdd(&pp[lane], acc0);
        atomicAdd(&pp[lane + 32], acc1);
        if (lane < 8) atomicAdd(&pp[lane + 64], acc2);
    }
    __syncthreads();
    if (tid < PPAR) {
        float v = pp[tid] + b2[tid];
        pp[tid] = v;
        if (grp == 0) g_params[b * PPAR + tid] = v;
    }
    __syncthreads();
    // ==== gate trig ====
    if (tid < NGATES) {
        float* dst = &gf[tid * 4];
        dst[0] = cosf(0.5f * pp[2 * tid]);
        dst[1] = sinf(0.5f * pp[2 * tid]);
        dst[2] = cosf(0.5f * pp[2 * tid + 1]);
        dst[3] = sinf(0.5f * pp[2 * tid + 1]);
    }
    __syncthreads();
    // ==== phase subtables ====
    if (tid < 128) {           // plo[L][l]: wires 4..8 (n bits 4..0)
        const int L = tid >> 5, l = tid & 31;
        float pr = 1.f, pi_ = 0.f;
#pragma unroll
        for (int w = 4; w < 9; w++) {
            float cp = gf[(L * 9 + w) * 4 + 2];
            float sp = gf[(L * 9 + w) * 4 + 3];
            float sg = ((l >> (8 - w)) & 1) ? sp : -sp;
            float nr = fmaf(pr, cp, -pi_ * sg);
            float ni = fmaf(pr, sg,  pi_ * cp);
            pr = nr; pi_ = ni;
        }
        plo[L * 32 + l] = make_float2(pr, pi_);
    } else if (tid < 192) {    // phi[L][hh]: wires 0..3 (n bits 8..5), C_L folded (L>=1)
        const int L = (tid - 128) >> 4, hh = tid & 15;
        float pr = 1.f, pi_ = 0.f;
#pragma unroll
        for (int w = 0; w < 4; w++) {
            float cp = gf[(L * 9 + w) * 4 + 2];
            float sp = gf[(L * 9 + w) * 4 + 3];
            float sg = ((hh >> (3 - w)) & 1) ? sp : -sp;
            float nr = fmaf(pr, cp, -pi_ * sg);
            float ni = fmaf(pr, sg,  pi_ * cp);
            pr = nr; pi_ = ni;
        }
        if (L >= 1) {
            float C = 1.f;
#pragma unroll
            for (int w = 0; w < 9; w++) C *= gf[(L * 9 + w) * 4];
            pr *= C; pi_ *= C;
        }
        phi[L * 16 + hh] = make_float2(pr, pi_);
    }
    __syncthreads();
    // ==== full tables: ph[L][.] = plo*phi ====
    // L0: layout-A index of p = pinv9(n): ((p&15)<<5)|(p>>4).  L1-3: linear n.
    {
        const int n = tid;
#pragma unroll
        for (int L = 0; L < NLAYERS; L++) {
            float2 lo = plo[L * 32 + (n & 31)];
            float2 hi = phi[L * 16 + (n >> 5)];
            float pr  = fmaf(lo.x, hi.x, -lo.y * hi.y);
            float pi_ = fmaf(lo.x, hi.y,  lo.y * hi.x);
            int idx = n;
            if (L == 0) {
                int p = pinv9(n);
                idx = ((p & 15) << 5) | (p >> 4);
            }
            ph[L * 512 + idx] = make_float2(pr, pi_);
        }
    }
    __syncthreads();

    const int l0 = lane & 1, l1 = (lane >> 1) & 1, l2 = (lane >> 2) & 1;
    const int l3 = (lane >> 3) & 1, l4 = (lane >> 4) & 1;

    float re[16], im[16];

    // ---- layer 0: analytic (validated R4-R13) ----
    {
        float E0a, E0b, E1a, E1b, E2a, E2b, E3a, E3b, E4a, E4b;
        float E5a, E5b, E6a, E6b, E7a, E7b, E8a, E8b;
#define MKE(W, A, Bv) { float c_ = gf[(W)*4], s_ = gf[(W)*4+1]; \
        int cb = (col >> (8-(W))) & 1; A = cb ? -s_ : c_; Bv = cb ? c_ : s_; }
        MKE(0, E0a, E0b) MKE(1, E1a, E1b) MKE(2, E2a, E2b)
        MKE(3, E3a, E3b) MKE(4, E4a, E4b) MKE(5, E5a, E5b)
        MKE(6, E6a, E6b) MKE(7, E7a, E7b) MKE(8, E8a, E8b)
#undef MKE
        float Plane = ((l0 ^ l1) ? E4b : E4a)
                    * ((l1 ^ l2) ? E3b : E3a)
                    * ((l2 ^ l3) ? E2b : E2a);
        float q3_0 = l0 ? E5b : E5a;
        float q3_1 = l0 ? E5a : E5b;
        int x34 = l3 ^ l4;
        float q78_0 = (x34 ? E1b : E1a) * (l4 ? E0b : E0a);
        float q78_1 = (x34 ? E1a : E1b) * (l4 ? E0a : E0b);
#pragma unroll
        for (int r = 0; r < 16; r++) {
            const int r0 = r & 1, r1 = (r >> 1) & 1, r2 = (r >> 2) & 1, r3 = (r >> 3) & 1;
            float amp = Plane
                      * (r3 ? q3_1 : q3_0)
                      * (r0 ? q78_1 : q78_0)
                      * ((r0 ^ r1) ? E8b : E8a)
                      * ((r1 ^ r2) ? E7b : E7a)
                      * ((r2 ^ r3) ? E6b : E6a);
            float2 p0 = ph[(r << 5) | lane];
            re[r] = amp * p0.x;
            im[r] = amp * p0.y;
        }
    }

    // exchange addressing (validated R8/R13)
    float2* wb = buf2 + wid * 512;
    const int awb = (lane << 4) ^ lane;         // A-write: addr = awb ^ r
    const int lb  = lane ^ (lane >> 4);         // B-read:  addr = s*34 ^ lb
    const int paBase = f2s(cperm(lane << 4));   // exact

#pragma unroll 1
    for (int L = 1; L < NLAYERS; L++) {
        const float* gL = gf + L * 36;
        // ---- layout A: wires 5..8, fast-Givens ----
#pragma unroll
        for (int w = 5; w < 9; w++) {
            float tg = __fdividef(gL[w * 4 + 1], gL[w * 4]);
            const int bit = 1 << (8 - w);
#pragma unroll
            for (int ra = 0; ra < 16; ra++) {
                if (ra & bit) continue;
                const int rb = ra | bit;
                float xr = re[ra], yr = re[rb];
                re[ra] = fmaf(-tg, yr, xr);
                re[rb] = fmaf( tg, xr, yr);
                float xi = im[ra], yi = im[rb];
                im[ra] = fmaf(-tg, yi, xi);
                im[rb] = fmaf( tg, xi, yi);
            }
        }
        // ---- transpose A->B write (float2, swizzle x^(x>>4)) ----
#pragma unroll
        for (int r = 0; r < 16; r++) wb[awb ^ r] = make_float2(re[r], im[r]);
        __syncwarp();
        // ---- transpose A->B read WITH wire-4 gate fused ----
        // Gates commute across wires; wire 4 = lane bit 4 in layout B.
        // Partner (lane^16) of slot s sits at addr^17.
        {
            float tg4 = __fdividef(gL[4 * 4 + 1], gL[4 * 4]);
            float bt4 = l4 ? tg4 : -tg4;
#pragma unroll
            for (int s = 0; s < 16; s++) {
                int a = (s * 34) ^ lb;
                float2 v  = wb[a];
                float2 vp = wb[a ^ 17];
                re[s] = fmaf(bt4, vp.x, v.x);
                im[s] = fmaf(bt4, vp.y, v.y);
            }
        }
        __syncwarp();
        // ---- layout B: wires 0..3 ----
#pragma unroll
        for (int w = 0; w < 4; w++) {
            float tg = __fdividef(gL[w * 4 + 1], gL[w * 4]);
            const int bit = 1 << (3 - w);
#pragma unroll
            for (int sa = 0; sa < 16; sa++) {
                if (sa & bit) continue;
                const int sb = sa | bit;
                float xr = re[sa], yr = re[sb];
                re[sa] = fmaf(-tg, yr, xr);
                re[sb] = fmaf( tg, xr, yr);
                float xi = im[sa], yi = im[sb];
                im[sa] = fmaf(-tg, yi, xi);
                im[sb] = fmaf( tg, xi, yi);
            }
        }
        if (L < 3) {
            // ---- phase (C_L folded), layout B: n = (s<<5)|lane ----
            const float2* phL = ph + L * 512;
#pragma unroll
            for (int s = 0; s < 16; s++) {
                float2 pq = phL[(s << 5) | lane];
                float tr = fmaf(pq.x, re[s], -(pq.y * im[s]));
                float ti = fmaf(pq.y, re[s],  (pq.x * im[s]));
                re[s] = tr; im[s] = ti;
            }
            // ---- transpose B->A with perm folded (float2, swizzle f2s) ----
#pragma unroll
            for (int s = 0; s < 16; s++) {
                int a = ((s << 5) ^ (s & 15) ^ ((s & 8) << 1)) ^ lane;
                wb[a] = make_float2(re[s], im[s]);
            }
            __syncwarp();
#pragma unroll
            for (int r = 0; r < 16; r++) {
                float2 v = wb[paBase ^ f2s(cperm(r))];
                re[r] = v.x; im[r] = v.y;
            }
            __syncwarp();
        } else {
            // ---- L3: phase re-only; layout B kept, perm folds into tile store ----
            const float2* phL = ph + 3 * 512;
#pragma unroll
            for (int s = 0; s < 16; s++) {
                float2 pq = phL[(s << 5) | lane];
                re[s] = fmaf(pq.x, re[s], -(pq.y * im[s]));
            }
        }
    }

    __syncthreads();   // all warps done with wb; alias buf as tile

    // direct tile store with CNOT perm folded: j = pinv9((s<<5)|lane)
    {
        const int pl = pinv9(lane);
#pragma unroll
        for (int s = 0; s < 16; s++)
            tile[wid][pinv9(s << 5) ^ pl] = re[s];
    }
    __syncthreads();

    // coalesced write: out[b][j][grp*16 + c]
    float* obase = out + (size_t)b * DDIM * DDIM + grp * 16;
    const int c  = tid & 15;
    const int j0 = tid >> 4;   // 0..31
#pragma unroll
    for (int k = 0; k < 16; k++) {
        int j = k * 32 + j0;
        obase[(size_t)j * DDIM + c] = tile[c][j];
    }
}

// ---------------------------------------------------------------------------
// K3: rank-2 expm update; Uv and ||v||^2 computed in-warp from the row.
// One warp per row (R13-validated; 2-row ILP variant was neutral).
// ---------------------------------------------------------------------------
__global__ void k3_update(float* __restrict__ out) {
    const int gw   = (blockIdx.x * blockDim.x + threadIdx.x) >> 5;
    const int lane = threadIdx.x & 31;
    const int b = gw >> 9;
    const int i = gw & 511;
    if (b >= BATCH) return;

    const float* gp = g_params + b * PPAR;
    float* row = out + ((size_t)b * DDIM + i) * DDIM;

    float r0 = row[lane];
    float r1 = row[lane + 32];
    float r2 = (lane < 8) ? row[lane + 64] : 0.f;
    float v0 = (lane >= 1) ? 0.01f * gp[lane] : 0.f;
    float v1 = 0.01f * gp[lane + 32];
    float v2 = (lane < 8) ? 0.01f * gp[lane + 64] : 0.f;
    float u0 = __shfl_sync(0xffffffffu, r0, 0);

    float uv = fmaf(r0, v0, fmaf(r1, v1, r2 * v2));
    float s2 = fmaf(v0, v0, fmaf(v1, v1, v2 * v2));
#pragma unroll
    for (int d = 16; d >= 1; d >>= 1) {
        uv += __shfl_xor_sync(0xffffffffu, uv, d);
        s2 += __shfl_xor_sync(0xffffffffu, s2, d);
    }

    float th = sqrtf(s2);
    float ct = cosf(th);
    float a1, a2;
    if (th > 1e-6f) { a1 = sinf(th) / th; a2 = (1.f - ct) / s2; }
    else            { a1 = 1.f - s2 * (1.f / 6.f); a2 = 0.5f; }
    float f = fmaf(a1, u0, -a2 * uv);

    row[lane]      = (lane == 0) ? fmaf(u0, ct, -a1 * uv) : fmaf(f, v0, r0);
    row[lane + 32] = fmaf(f, v1, r1);
    if (lane < 8) row[lane + 64] = fmaf(f, v2, r2);
}

// ---------------------------------------------------------------------------
extern "C" void kernel_launch(void* const* d_in, const int* in_sizes, int n_in,
                              void* d_out, int out_size) {
    const float* t  = (const float*)d_in[0];
    const float* w1 = (const float*)d_in[1];
    const float* b1 = (const float*)d_in[2];
    const float* w2 = (const float*)d_in[3];
    const float* b2 = (const float*)d_in[4];
    float* out = (float*)d_out;

    cudaFuncSetAttribute(k2_sim, cudaFuncAttributeMaxDynamicSharedMemorySize,
                         SM_TOTAL);

    k2_sim<<<BATCH * 32, 512, SM_TOTAL>>>(out, t, w1, b1, w2, b2);
    k3_update<<<(BATCH * DDIM) / 8, 256>>>(out);
}

// round 16
// speedup vs baseline: 1.8348x; 1.2524x over previous
#include <cuda_runtime.h>
#include <math.h>

#define NWIRES 9
#define NLAYERS 4
#define DDIM 512
#define BATCH 64
#define PPAR 72
#define NGATES 36
#define EMBED 512

// Scratch (allocation-free device globals)
__device__ float  g_params[BATCH * PPAR];
__device__ float  g_gf[BATCH * 144];          // per-gate {c,s,cp,sp}
__device__ float  g_scal[BATCH * 4];          // a1, a2, cos th
__device__ float2 g_ph[BATCH * 4 * 512];      // phase tables (L0 pre-indexed)

// dynamic smem layout for the sim kernel
#define SM_GF   0                        // 144 floats (576B)
#define SM_PH   576                      // float2[4][512] = 16384 B
#define SM_BUF  16960                    // 16 warps x 512 float2 = 65536 B
#define SM_TOTAL (16960 + 65536)

// CNOT-ring permutation (verified R1): new[n] = old[pi(n)]
__device__ __forceinline__ int cperm(int p) {
    int n = (p ^ (p >> 1)) & 0x7F;
    n |= (((p >> 7) ^ (p >> 8) ^ p) & 1) << 7;
    n |= (((p >> 8) ^ p) & 1) << 8;
    return n;
}
// inverse of cperm (GF(2)-linear; validated R4-R15)
__device__ __forceinline__ int pinv9(int n) {
    int pb = __popc(n) & 1;
    int acc = pb, run = pb;
#pragma unroll
    for (int j = 0; j < 7; j++) { run ^= (n >> j) & 1; acc |= run << (j + 1); }
    acc |= (((n >> 8) & 1) ^ pb) << 8;
    return acc;
}
// B->A swizzle (GF(2)-rank-verified conflict-free)
__device__ __forceinline__ int f2s(int a) {
    return a ^ ((a >> 5) & 15) ^ ((a >> 4) & 16);
}

// ---------------------------------------------------------------------------
// K0: per-batch precompute (64 blocks, one wave). MLP -> params; gate trig;
// factorized phase subtables; full tables (L0 at layout-A index of pinv9(n));
// rank-2 scalars. All results to device globals consumed by k2/k3.
// ---------------------------------------------------------------------------
__global__ __launch_bounds__(512) void k0_prep(
        const float* __restrict__ t,  const float* __restrict__ w1,
        const float* __restrict__ b1, const float* __restrict__ w2,
        const float* __restrict__ b2) {
    const int b   = blockIdx.x;
    const int tid = threadIdx.x;
    const int wid = tid >> 5, lane = tid & 31;

    __shared__ float  h[EMBED];
    __shared__ float  pp[PPAR];
    __shared__ float  gf[144];
    __shared__ float2 plo[4 * 32];
    __shared__ float2 phi[4 * 16];

    // MLP: params = silu(t*w1+b1) @ w2 + b2
    {
        float tv = t[b];
        float x = fmaf(tv, w1[tid], b1[tid]);
        if (tid < PPAR) pp[tid] = 0.f;
        h[tid] = x / (1.f + expf(-x));
    }
    __syncthreads();
    {
        float acc0 = 0.f, acc1 = 0.f, acc2 = 0.f;
        const float* w2base = w2 + (wid * 32) * PPAR;
#pragma unroll 8
        for (int k = 0; k < 32; k++) {
            float hv = h[wid * 32 + k];
            const float* wrow = w2base + k * PPAR;
            acc0 = fmaf(hv, wrow[lane], acc0);
            acc1 = fmaf(hv, wrow[lane + 32], acc1);
            if (lane < 8) acc2 = fmaf(hv, wrow[lane + 64], acc2);
        }
        atomicAdd(&pp[lane], acc0);
        atomicAdd(&pp[lane + 32], acc1);
        if (lane < 8) atomicAdd(&pp[lane + 64], acc2);
    }
    __syncthreads();
    if (tid < PPAR) {
        float v = pp[tid] + b2[tid];
        pp[tid] = v;
        g_params[b * PPAR + tid] = v;
    }
    __syncthreads();
    // gate trig + rank-2 scalars
    if (tid < NGATES) {
        float* dst = &gf[tid * 4];
        dst[0] = cosf(0.5f * pp[2 * tid]);
        dst[1] = sinf(0.5f * pp[2 * tid]);
        dst[2] = cosf(0.5f * pp[2 * tid + 1]);
        dst[3] = sinf(0.5f * pp[2 * tid + 1]);
    }
    if (tid == 64) {   // different warp than trig; reads pp (post-sync)
        float s2 = 0.f;
        for (int j = 1; j < PPAR; j++) { float vj = 0.01f * pp[j]; s2 = fmaf(vj, vj, s2); }
        float th = sqrtf(s2);
        float ct = cosf(th);
        float a1, a2;
        if (th > 1e-6f) { a1 = sinf(th) / th; a2 = (1.f - ct) / s2; }
        else            { a1 = 1.f - s2 * (1.f / 6.f); a2 = 0.5f; }
        g_scal[b * 4 + 0] = a1;
        g_scal[b * 4 + 1] = a2;
        g_scal[b * 4 + 2] = ct;
    }
    __syncthreads();
    if (tid < 144) g_gf[b * 144 + tid] = gf[tid];
    // phase subtables
    if (tid < 128) {           // plo[L][l]: wires 4..8 (n bits 4..0)
        const int L = tid >> 5, l = tid & 31;
        float pr = 1.f, pi_ = 0.f;
#pragma unroll
        for (int w = 4; w < 9; w++) {
            float cp = gf[(L * 9 + w) * 4 + 2];
            float sp = gf[(L * 9 + w) * 4 + 3];
            float sg = ((l >> (8 - w)) & 1) ? sp : -sp;
            float nr = fmaf(pr, cp, -pi_ * sg);
            float ni = fmaf(pr, sg,  pi_ * cp);
            pr = nr; pi_ = ni;
        }
        plo[L * 32 + l] = make_float2(pr, pi_);
    } else if (tid < 192) {    // phi[L][hh]: wires 0..3 (n bits 8..5), C_L folded (L>=1)
        const int L = (tid - 128) >> 4, hh = tid & 15;
        float pr = 1.f, pi_ = 0.f;
#pragma unroll
        for (int w = 0; w < 4; w++) {
            float cp = gf[(L * 9 + w) * 4 + 2];
            float sp = gf[(L * 9 + w) * 4 + 3];
            float sg = ((hh >> (3 - w)) & 1) ? sp : -sp;
            float nr = fmaf(pr, cp, -pi_ * sg);
            float ni = fmaf(pr, sg,  pi_ * cp);
            pr = nr; pi_ = ni;
        }
        if (L >= 1) {
            float C = 1.f;
#pragma unroll
            for (int w = 0; w < 9; w++) C *= gf[(L * 9 + w) * 4];
            pr *= C; pi_ *= C;
        }
        phi[L * 16 + hh] = make_float2(pr, pi_);
    }
    __syncthreads();
    // full tables: L0 at layout-A index of p=pinv9(n); L1-3 at linear n
    {
        const int n = tid;
        float2* dst = g_ph + b * 2048;
#pragma unroll
        for (int L = 0; L < NLAYERS; L++) {
            float2 lo = plo[L * 32 + (n & 31)];
            float2 hi = phi[L * 16 + (n >> 5)];
            float pr  = fmaf(lo.x, hi.x, -lo.y * hi.y);
            float pi_ = fmaf(lo.x, hi.y,  lo.y * hi.x);
            int idx = n;
            if (L == 0) {
                int p = pinv9(n);
                idx = ((p & 15) << 5) | (p >> 4);
            }
            dst[L * 512 + idx] = make_float2(pr, pi_);
        }
    }
}

// ---------------------------------------------------------------------------
// K2: circuit simulation. One column per warp. Mainloop identical to R15:
// Layout A: lane=p[8:4], slot=p[3:0]; layout B: lane=p[4:0], slot=p[8:5].
// Wire 4 fused into the A->B transpose read (partner at addr^17).
// Prologue is now just a 17KB table load from k0's globals.
// ---------------------------------------------------------------------------
__global__ __launch_bounds__(512, 2) void k2_sim(float* __restrict__ out) {
    const int b    = blockIdx.x >> 5;   // batch
    const int grp  = blockIdx.x & 31;   // 32 groups x 16 columns
    const int wid  = threadIdx.x >> 5;
    const int lane = threadIdx.x & 31;
    const int col  = grp * 16 + wid;
    const int tid  = threadIdx.x;

    extern __shared__ char dsm[];
    float*  gf   = (float*)(dsm + SM_GF);          // 144 floats
    float2* ph   = (float2*)(dsm + SM_PH);         // [4][512]
    float2* buf2 = (float2*)(dsm + SM_BUF);        // 16 warps x 512 float2
    float (*tile)[513] = (float (*)[513])buf2;     // epilogue alias

    // ==== prologue: load precomputed tables ====
    {
        const float4* src = (const float4*)(g_ph + (size_t)b * 2048);
        float4* dst = (float4*)ph;
        dst[tid]       = src[tid];
        dst[tid + 512] = src[tid + 512];
        if (tid < 144) gf[tid] = g_gf[b * 144 + tid];
    }
    __syncthreads();

    const int l0 = lane & 1, l1 = (lane >> 1) & 1, l2 = (lane >> 2) & 1;
    const int l3 = (lane >> 3) & 1, l4 = (lane >> 4) & 1;

    float re[16], im[16];

    // ---- layer 0: analytic (validated R4-R15) ----
    {
        float E0a, E0b, E1a, E1b, E2a, E2b, E3a, E3b, E4a, E4b;
        float E5a, E5b, E6a, E6b, E7a, E7b, E8a, E8b;
#define MKE(W, A, Bv) { float c_ = gf[(W)*4], s_ = gf[(W)*4+1]; \
        int cb = (col >> (8-(W))) & 1; A = cb ? -s_ : c_; Bv = cb ? c_ : s_; }
        MKE(0, E0a, E0b) MKE(1, E1a, E1b) MKE(2, E2a, E2b)
        MKE(3, E3a, E3b) MKE(4, E4a, E4b) MKE(5, E5a, E5b)
        MKE(6, E6a, E6b) MKE(7, E7a, E7b) MKE(8, E8a, E8b)
#undef MKE
        float Plane = ((l0 ^ l1) ? E4b : E4a)
                    * ((l1 ^ l2) ? E3b : E3a)
                    * ((l2 ^ l3) ? E2b : E2a);
        float q3_0 = l0 ? E5b : E5a;
        float q3_1 = l0 ? E5a : E5b;
        int x34 = l3 ^ l4;
        float q78_0 = (x34 ? E1b : E1a) * (l4 ? E0b : E0a);
        float q78_1 = (x34 ? E1a : E1b) * (l4 ? E0a : E0b);
#pragma unroll
        for (int r = 0; r < 16; r++) {
            const int r0 = r & 1, r1 = (r >> 1) & 1, r2 = (r >> 2) & 1, r3 = (r >> 3) & 1;
            float amp = Plane
                      * (r3 ? q3_1 : q3_0)
                      * (r0 ? q78_1 : q78_0)
                      * ((r0 ^ r1) ? E8b : E8a)
                      * ((r1 ^ r2) ? E7b : E7a)
                      * ((r2 ^ r3) ? E6b : E6a);
            float2 p0 = ph[(r << 5) | lane];
            re[r] = amp * p0.x;
            im[r] = amp * p0.y;
        }
    }

    // exchange addressing (validated R8-R15)
    float2* wb = buf2 + wid * 512;
    const int awb = (lane << 4) ^ lane;         // A-write: addr = awb ^ r
    const int lb  = lane ^ (lane >> 4);         // B-read:  addr = s*34 ^ lb
    const int paBase = f2s(cperm(lane << 4));   // exact

#pragma unroll 1
    for (int L = 1; L < NLAYERS; L++) {
        const float* gL = gf + L * 36;
        // ---- layout A: wires 5..8, fast-Givens ----
#pragma unroll
        for (int w = 5; w < 9; w++) {
            float tg = __fdividef(gL[w * 4 + 1], gL[w * 4]);
            const int bit = 1 << (8 - w);
#pragma unroll
            for (int ra = 0; ra < 16; ra++) {
                if (ra & bit) continue;
                const int rb = ra | bit;
                float xr = re[ra], yr = re[rb];
                re[ra] = fmaf(-tg, yr, xr);
                re[rb] = fmaf( tg, xr, yr);
                float xi = im[ra], yi = im[rb];
                im[ra] = fmaf(-tg, yi, xi);
                im[rb] = fmaf( tg, xi, yi);
            }
        }
        // ---- transpose A->B write (float2, swizzle x^(x>>4)) ----
#pragma unroll
        for (int r = 0; r < 16; r++) wb[awb ^ r] = make_float2(re[r], im[r]);
        __syncwarp();
        // ---- transpose A->B read WITH wire-4 gate fused (partner addr^17) ----
        {
            float tg4 = __fdividef(gL[4 * 4 + 1], gL[4 * 4]);
            float bt4 = l4 ? tg4 : -tg4;
#pragma unroll
            for (int s = 0; s < 16; s++) {
                int a = (s * 34) ^ lb;
                float2 v  = wb[a];
                float2 vp = wb[a ^ 17];
                re[s] = fmaf(bt4, vp.x, v.x);
                im[s] = fmaf(bt4, vp.y, v.y);
            }
        }
        __syncwarp();
        // ---- layout B: wires 0..3 ----
#pragma unroll
        for (int w = 0; w < 4; w++) {
            float tg = __fdividef(gL[w * 4 + 1], gL[w * 4]);
            const int bit = 1 << (3 - w);
#pragma unroll
            for (int sa = 0; sa < 16; sa++) {
                if (sa & bit) continue;
                const int sb = sa | bit;
                float xr = re[sa], yr = re[sb];
                re[sa] = fmaf(-tg, yr, xr);
                re[sb] = fmaf( tg, xr, yr);
                float xi = im[sa], yi = im[sb];
                im[sa] = fmaf(-tg, yi, xi);
                im[sb] = fmaf( tg, xi, yi);
            }
        }
        if (L < 3) {
            // ---- phase (C_L folded), layout B: n = (s<<5)|lane ----
            const float2* phL = ph + L * 512;
#pragma unroll
            for (int s = 0; s < 16; s++) {
                float2 pq = phL[(s << 5) | lane];
                float tr = fmaf(pq.x, re[s], -(pq.y * im[s]));
                float ti = fmaf(pq.y, re[s],  (pq.x * im[s]));
                re[s] = tr; im[s] = ti;
            }
            // ---- transpose B->A with perm folded (float2, swizzle f2s) ----
#pragma unroll
            for (int s = 0; s < 16; s++) {
                int a = ((s << 5) ^ (s & 15) ^ ((s & 8) << 1)) ^ lane;
                wb[a] = make_float2(re[s], im[s]);
            }
            __syncwarp();
#pragma unroll
            for (int r = 0; r < 16; r++) {
                float2 v = wb[paBase ^ f2s(cperm(r))];
                re[r] = v.x; im[r] = v.y;
            }
            __syncwarp();
        } else {
            // ---- L3: phase re-only; layout B kept, perm folds into tile store ----
            const float2* phL = ph + 3 * 512;
#pragma unroll
            for (int s = 0; s < 16; s++) {
                float2 pq = phL[(s << 5) | lane];
                re[s] = fmaf(pq.x, re[s], -(pq.y * im[s]));
            }
        }
    }

    __syncthreads();   // all warps done with wb; alias buf as tile

    // direct tile store with CNOT perm folded: j = pinv9((s<<5)|lane)
    {
        const int pl = pinv9(lane);
#pragma unroll
        for (int s = 0; s < 16; s++)
            tile[wid][pinv9(s << 5) ^ pl] = re[s];
    }
    __syncthreads();

    // coalesced write: out[b][j][grp*16 + c]
    float* obase = out + (size_t)b * DDIM * DDIM + grp * 16;
    const int c  = tid & 15;
    const int j0 = tid >> 4;   // 0..31
#pragma unroll
    for (int k = 0; k < 16; k++) {
        int j = k * 32 + j0;
        obase[(size_t)j * DDIM + c] = tile[c][j];
    }
}

// ---------------------------------------------------------------------------
// K3: rank-2 expm update; Uv in-warp, scalars precomputed by k0.
// One warp per row. C[i,j] += (a1*u0 - a2*Uv_i) v_j (j>=1);
// C[i,0] = ct*u0 - a1*Uv_i.
// ---------------------------------------------------------------------------
__global__ void k3_update(float* __restrict__ out) {
    const int gw   = (blockIdx.x * blockDim.x + threadIdx.x) >> 5;
    const int lane = threadIdx.x & 31;
    const int b = gw >> 9;
    const int i = gw & 511;
    if (b >= BATCH) return;

    const float* gp = g_params + b * PPAR;
    float* row = out + ((size_t)b * DDIM + i) * DDIM;

    float r0 = row[lane];
    float r1 = row[lane + 32];
    float r2 = (lane < 8) ? row[lane + 64] : 0.f;
    float v0 = (lane >= 1) ? 0.01f * gp[lane] : 0.f;
    float v1 = 0.01f * gp[lane + 32];
    float v2 = (lane < 8) ? 0.01f * gp[lane + 64] : 0.f;
    float u0 = __shfl_sync(0xffffffffu, r0, 0);

    float uv = fmaf(r0, v0, fmaf(r1, v1, r2 * v2));
#pragma unroll
    for (int d = 16; d >= 1; d >>= 1)
        uv += __shfl_xor_sync(0xffffffffu, uv, d);

    float a1 = g_scal[b * 4 + 0];
    float a2 = g_scal[b * 4 + 1];
    float ct = g_scal[b * 4 + 2];
    float f = fmaf(a1, u0, -a2 * uv);

    row[lane]      = (lane == 0) ? fmaf(u0, ct, -a1 * uv) : fmaf(f, v0, r0);
    row[lane + 32] = fmaf(f, v1, r1);
    if (lane < 8) row[lane + 64] = fmaf(f, v2, r2);
}

// ---------------------------------------------------------------------------
extern "C" void kernel_launch(void* const* d_in, const int* in_sizes, int n_in,
                              void* d_out, int out_size) {
    const float* t  = (const float*)d_in[0];
    const float* w1 = (const float*)d_in[1];
    const float* b1 = (const float*)d_in[2];
    const float* w2 = (const float*)d_in[3];
    const float* b2 = (const float*)d_in[4];
    float* out = (float*)d_out;

    cudaFuncSetAttribute(k2_sim, cudaFuncAttributeMaxDynamicSharedMemorySize,
                         SM_TOTAL);

    k0_prep<<<BATCH, 512>>>(t, w1, b1, w2, b2);
    k2_sim<<<BATCH * 32, 512, SM_TOTAL>>>(out);
    k3_update<<<(BATCH * DDIM) / 8, 256>>>(out);
}